// round 2
// baseline (speedup 1.0000x reference)
#include <cuda_runtime.h>
#include <cstdint>

#define D_MODEL 2048
#define SEQ     1024
#define NHEADS  256
#define HDIM    8
#define OUT_ELEMS (SEQ*D_MODEL)            // 2097152
// scores elems = 256*1024*1024 = 268435456

// ---------------- scratch (no allocations allowed) ----------------
__device__ float g_q[SEQ*D_MODEL];   // 8 MB
__device__ float g_y[SEQ*D_MODEL];   // 8 MB
__device__ float g_k[SEQ*HDIM];
__device__ float g_v[SEQ*HDIM];

static __device__ __forceinline__ unsigned f2tf(float x){
    unsigned r; asm("cvt.rna.tf32.f32 %0, %1;" : "=r"(r) : "f"(x)); return r;
}

#define MMA8(d, a, b) asm volatile( \
  "mma.sync.aligned.m16n8k8.row.col.f32.tf32.tf32.f32 " \
  "{%0,%1,%2,%3},{%4,%5,%6,%7},{%8,%9},{%0,%1,%2,%3};\n" \
  : "+f"(d[0]), "+f"(d[1]), "+f"(d[2]), "+f"(d[3]) \
  : "r"(a[0]),"r"(a[1]),"r"(a[2]),"r"(a[3]), "r"(b[0]),"r"(b[1]))

// ================= 3xTF32 GEMM: C = A[MxK] @ B[KxN] + bias ==================
// BM=128 BN=128 BK=16, 256 threads, warp grid 4x2, warp tile 32x64.
// hi/lo TF32 split gives ~fp32 accuracy (error ~2^-22).
#define GBM 128
#define GBN 128
#define GBK 16
#define ASTR 20     // 16+4 pad: conflict-free A-frag reads
#define BSTR 136    // 128+8 pad: conflict-free B-frag reads

__global__ __launch_bounds__(256) void gemm3tf32(
    const float* __restrict__ A, const float* __restrict__ B,
    const float* __restrict__ bias, float* __restrict__ C,
    int M, int N, int K)
{
    __shared__ unsigned Ah[GBM*ASTR], Al[GBM*ASTR];
    __shared__ unsigned Bh[GBK*BSTR], Bl[GBK*BSTR];
    const int tid = threadIdx.x;
    const int warp = tid >> 5, lane = tid & 31;
    const int wm = warp >> 1, wn = warp & 1;
    const int m0 = blockIdx.y * GBM, n0 = blockIdx.x * GBN;

    float acc[2][8][4];
    #pragma unroll
    for (int a = 0; a < 2; a++)
        #pragma unroll
        for (int b = 0; b < 8; b++)
            #pragma unroll
            for (int c = 0; c < 4; c++) acc[a][b][c] = 0.f;

    float4 ar[2], br[2];
    const int KT = K / GBK;

    // prefetch tile 0 into registers
    #pragma unroll
    for (int r = 0; r < 2; r++){
        int f = tid + 256*r;
        int row = f >> 2, c4 = f & 3;          // A: 128 rows x 4 float4
        ar[r] = *(const float4*)(A + (size_t)(m0+row)*K + c4*4);
        int brow = f >> 5, bc4 = f & 31;       // B: 16 rows x 32 float4
        br[r] = *(const float4*)(B + (size_t)brow*N + n0 + bc4*4);
    }

    for (int kt = 0; kt < KT; ++kt){
        // stage regs -> smem with hi/lo tf32 split
        #pragma unroll
        for (int r = 0; r < 2; r++){
            int f = tid + 256*r;
            int row = f >> 2, c4 = f & 3;
            float av[4] = {ar[r].x, ar[r].y, ar[r].z, ar[r].w};
            #pragma unroll
            for (int e = 0; e < 4; e++){
                unsigned hb = f2tf(av[e]);
                float hf = __uint_as_float(hb);
                Ah[row*ASTR + c4*4 + e] = hb;
                Al[row*ASTR + c4*4 + e] = f2tf(av[e] - hf);
            }
            int brow = f >> 5, bc4 = f & 31;
            float bv4[4] = {br[r].x, br[r].y, br[r].z, br[r].w};
            #pragma unroll
            for (int e = 0; e < 4; e++){
                unsigned hb = f2tf(bv4[e]);
                float hf = __uint_as_float(hb);
                Bh[brow*BSTR + bc4*4 + e] = hb;
                Bl[brow*BSTR + bc4*4 + e] = f2tf(bv4[e] - hf);
            }
        }
        __syncthreads();
        if (kt + 1 < KT){  // issue next-tile global loads; latency hides under compute
            int k0 = (kt+1)*GBK;
            #pragma unroll
            for (int r = 0; r < 2; r++){
                int f = tid + 256*r;
                int row = f >> 2, c4 = f & 3;
                ar[r] = *(const float4*)(A + (size_t)(m0+row)*K + k0 + c4*4);
                int brow = f >> 5, bc4 = f & 31;
                br[r] = *(const float4*)(B + (size_t)(k0+brow)*N + n0 + bc4*4);
            }
        }
        #pragma unroll
        for (int ks = 0; ks < 2; ++ks){
            unsigned ah[2][4], al2[2][4], bh[8][2], bl2[8][2];
            #pragma unroll
            for (int mt = 0; mt < 2; ++mt){
                int r = wm*32 + mt*16 + (lane >> 2);
                int c = ks*8 + (lane & 3);
                ah[mt][0]=Ah[r*ASTR+c];      ah[mt][1]=Ah[(r+8)*ASTR+c];
                ah[mt][2]=Ah[r*ASTR+c+4];    ah[mt][3]=Ah[(r+8)*ASTR+c+4];
                al2[mt][0]=Al[r*ASTR+c];     al2[mt][1]=Al[(r+8)*ASTR+c];
                al2[mt][2]=Al[r*ASTR+c+4];   al2[mt][3]=Al[(r+8)*ASTR+c+4];
            }
            #pragma unroll
            for (int nt = 0; nt < 8; ++nt){
                int col = wn*64 + nt*8 + (lane >> 2);
                int row = ks*8 + (lane & 3);
                bh[nt][0]=Bh[row*BSTR+col];      bh[nt][1]=Bh[(row+4)*BSTR+col];
                bl2[nt][0]=Bl[row*BSTR+col];     bl2[nt][1]=Bl[(row+4)*BSTR+col];
            }
            #pragma unroll
            for (int mt = 0; mt < 2; ++mt)
                #pragma unroll
                for (int nt = 0; nt < 8; ++nt){
                    MMA8(acc[mt][nt], ah[mt],  bh[nt]);
                    MMA8(acc[mt][nt], ah[mt],  bl2[nt]);
                    MMA8(acc[mt][nt], al2[mt], bh[nt]);
                }
        }
        __syncthreads();
    }

    #pragma unroll
    for (int mt = 0; mt < 2; ++mt){
        int r = m0 + wm*32 + mt*16 + (lane >> 2);
        #pragma unroll
        for (int nt = 0; nt < 8; ++nt){
            int cb = n0 + wn*64 + nt*8 + 2*(lane & 3);
            float b0 = bias[cb], b1 = bias[cb+1];
            float2 v0 = make_float2(acc[mt][nt][0]+b0, acc[mt][nt][1]+b1);
            float2 v1 = make_float2(acc[mt][nt][2]+b0, acc[mt][nt][3]+b1);
            *(float2*)(C + (size_t)r*N + cb)     = v0;
            *(float2*)(C + (size_t)(r+8)*N + cb) = v1;
        }
    }
}

// ================= k/v projections: x[1024x2048] @ W[2048x8] + b ===========
__global__ __launch_bounds__(128) void kv_gemm(
    const float* __restrict__ x,
    const float* __restrict__ Wk, const float* __restrict__ bk,
    const float* __restrict__ Wv, const float* __restrict__ bv,
    float* __restrict__ kout, float* __restrict__ vout)
{
    __shared__ float xs[D_MODEL];
    const int i = blockIdx.x, tid = threadIdx.x;
    #pragma unroll
    for (int r = 0; r < 4; r++){
        int f = tid + 128*r;
        ((float4*)xs)[f] = ((const float4*)(x + (size_t)i*D_MODEL))[f];
    }
    __syncthreads();
    const int warp = tid >> 5, lane = tid & 31;
    for (int cc = 0; cc < 4; ++cc){
        int col = warp*4 + cc;                 // 0..15: 0-7 -> K, 8-15 -> V
        const float* W = (col < 8) ? Wk : Wv;
        int c = col & 7;
        float acc = 0.f;
        for (int j = lane; j < D_MODEL; j += 32)
            acc = fmaf(xs[j], W[j*8 + c], acc);
        #pragma unroll
        for (int off = 16; off; off >>= 1)
            acc += __shfl_xor_sync(0xffffffffu, acc, off);
        if (lane == 0){
            float b = (col < 8) ? bk[c] : bv[c];
            ((col < 8) ? kout : vout)[i*8 + c] = acc + b;
        }
    }
}

// ================= fused causal MQA attention ==============================
// K,V fully resident in SMEM (transposed, padded). One warp handles a
// (query-row i, head-pair) unit; full 1024-wide score row lives in 32 regs/lane
// -> single pass over K, exact softmax, probs written once, AV accumulated
// in registers. Block b handles i=b and i=1023-b (constant work per block).
// NOTE: no min-blocks in launch_bounds — per-lane state is ~150 regs and a
// 2-CTA floor would force spills of the score arrays to local memory.
#define KSTR 1025
#define ATTN_SMEM ((16*KSTR + 2*D_MODEL)*4)   // 81984 bytes

__global__ __launch_bounds__(256) void attn_kernel(
    const float* __restrict__ q, const float* __restrict__ k,
    const float* __restrict__ v, float* __restrict__ scores,
    float* __restrict__ y)
{
    extern __shared__ float sm[];
    float* ksh = sm;                 // [8][KSTR]
    float* vsh = sm + 8*KSTR;        // [8][KSTR]
    float* qsh = sm + 16*KSTR;       // [2][2048]
    const int tid = threadIdx.x;
    const int i1 = blockIdx.x, i2 = (SEQ-1) - blockIdx.x;

    for (int idx = tid; idx < SEQ*HDIM; idx += 256){
        int j = idx >> 3, d = idx & 7;
        ksh[d*KSTR + j] = k[idx];
        vsh[d*KSTR + j] = v[idx];
    }
    for (int idx = tid; idx < D_MODEL; idx += 256){
        qsh[idx]           = q[(size_t)i1*D_MODEL + idx];
        qsh[D_MODEL + idx] = q[(size_t)i2*D_MODEL + idx];
    }
    __syncthreads();

    const int warp = tid >> 5, lane = tid & 31;
    const float SCALE = 0.35355339059327373f;   // 1/sqrt(8)
    const float L2E   = 1.4426950408889634f;

    for (int ii = 0; ii < 2; ++ii){
        const int i = ii ? i2 : i1;
        const float* qrow = qsh + ii*D_MODEL;
        const int T = (i >> 5) + 1;             // valid 32-wide chunks

        for (int g = warp; g < NHEADS/2; g += 8){
            const int h0 = 2*g, h1 = 2*g + 1;
            float qa[8], qb[8];
            #pragma unroll
            for (int d = 0; d < 8; ++d){
                qa[d] = qrow[h0*8+d]*SCALE;
                qb[d] = qrow[h1*8+d]*SCALE;
            }
            float s0[32], s1[32];
            float m0 = -1e30f, m1 = -1e30f;
            #pragma unroll
            for (int t = 0; t < 32; ++t){
                if (t < T){
                    int j = t*32 + lane;
                    float kf[8];
                    #pragma unroll
                    for (int d = 0; d < 8; ++d) kf[d] = ksh[d*KSTR + j];
                    float d0 = 0.f, d1 = 0.f;
                    #pragma unroll
                    for (int d = 0; d < 8; ++d){
                        d0 = fmaf(qa[d], kf[d], d0);
                        d1 = fmaf(qb[d], kf[d], d1);
                    }
                    bool val = (j <= i);
                    s0[t] = val ? d0 : -1e30f;
                    s1[t] = val ? d1 : -1e30f;
                    m0 = fmaxf(m0, s0[t]); m1 = fmaxf(m1, s1[t]);
                }
            }
            #pragma unroll
            for (int off = 16; off; off >>= 1){
                m0 = fmaxf(m0, __shfl_xor_sync(~0u, m0, off));
                m1 = fmaxf(m1, __shfl_xor_sync(~0u, m1, off));
            }
            float l0 = 0.f, l1 = 0.f;
            #pragma unroll
            for (int t = 0; t < 32; ++t){
                if (t < T){
                    float e0 = exp2f((s0[t]-m0)*L2E);
                    float e1 = exp2f((s1[t]-m1)*L2E);
                    s0[t] = e0; s1[t] = e1; l0 += e0; l1 += e1;
                }
            }
            #pragma unroll
            for (int off = 16; off; off >>= 1){
                l0 += __shfl_xor_sync(~0u, l0, off);
                l1 += __shfl_xor_sync(~0u, l1, off);
            }
            const float r0 = 1.f/l0, r1 = 1.f/l1;
            float a0[8], a1[8];
            #pragma unroll
            for (int d = 0; d < 8; ++d){ a0[d] = 0.f; a1[d] = 0.f; }
            const size_t row0 = ((size_t)h0*SEQ + i)*SEQ;
            const size_t row1 = ((size_t)h1*SEQ + i)*SEQ;
            #pragma unroll
            for (int t = 0; t < 32; ++t){
                int j = t*32 + lane;
                float p0 = 0.f, p1 = 0.f;
                if (t < T){ p0 = s0[t]*r0; p1 = s1[t]*r1; }
                if (scores){ scores[row0 + j] = p0; scores[row1 + j] = p1; }
                if (t < T){
                    #pragma unroll
                    for (int d = 0; d < 8; ++d){
                        float vf = vsh[d*KSTR + j];
                        a0[d] = fmaf(p0, vf, a0[d]);
                        a1[d] = fmaf(p1, vf, a1[d]);
                    }
                }
            }
            #pragma unroll
            for (int d = 0; d < 8; ++d){
                #pragma unroll
                for (int off = 16; off; off >>= 1){
                    a0[d] += __shfl_xor_sync(~0u, a0[d], off);
                    a1[d] += __shfl_xor_sync(~0u, a1[d], off);
                }
            }
            if (lane == 0){
                float* y0 = y + (size_t)i*D_MODEL + h0*8;
                *(float4*)(y0)     = make_float4(a0[0],a0[1],a0[2],a0[3]);
                *(float4*)(y0 + 4) = make_float4(a0[4],a0[5],a0[6],a0[7]);
                float* y1 = y + (size_t)i*D_MODEL + h1*8;
                *(float4*)(y1)     = make_float4(a1[0],a1[1],a1[2],a1[3]);
                *(float4*)(y1 + 4) = make_float4(a1[4],a1[5],a1[6],a1[7]);
            }
        }
    }
}

// ============================ launcher =====================================
extern "C" void kernel_launch(void* const* d_in, const int* in_sizes, int n_in,
                              void* d_out, int out_size)
{
    const float* x  = (const float*)d_in[0];
    // d_in[1] = mask (int32 tril) -- causal structure is known, unused
    const float* Wq = (const float*)d_in[2];
    const float* bq = (const float*)d_in[3];
    const float* Wk = (const float*)d_in[4];
    const float* bk = (const float*)d_in[5];
    const float* Wv = (const float*)d_in[6];
    const float* bv = (const float*)d_in[7];
    const float* Wo = (const float*)d_in[8];
    const float* bo = (const float*)d_in[9];

    float* out = (float*)d_out;
    float* scores = (out_size > OUT_ELEMS) ? (out + OUT_ELEMS) : nullptr;

    float *qg, *yg, *kg, *vg;
    cudaGetSymbolAddress((void**)&qg, g_q);
    cudaGetSymbolAddress((void**)&yg, g_y);
    cudaGetSymbolAddress((void**)&kg, g_k);
    cudaGetSymbolAddress((void**)&vg, g_v);

    cudaFuncSetAttribute(attn_kernel,
        cudaFuncAttributeMaxDynamicSharedMemorySize, ATTN_SMEM);

    // q = x @ Wq + bq
    gemm3tf32<<<dim3(D_MODEL/GBN, SEQ/GBM), 256>>>(x, Wq, bq, qg, SEQ, D_MODEL, D_MODEL);
    // k, v projections
    kv_gemm<<<SEQ, 128>>>(x, Wk, bk, Wv, bv, kg, vg);
    // fused attention: probs -> scores output, context -> g_y
    attn_kernel<<<SEQ/2, 256, ATTN_SMEM>>>(qg, kg, vg, scores, yg);
    // out = y @ Wo + bo
    gemm3tf32<<<dim3(D_MODEL/GBN, SEQ/GBM), 256>>>(yg, Wo, bo, out, SEQ, D_MODEL, D_MODEL);
}